// round 14
// baseline (speedup 1.0000x reference)
#include <cuda_runtime.h>
#include <cuda.h>
#include <cuda_fp16.h>
#include <cstdint>

#if defined(__CUDA_ARCH__) && defined(__CUDA_ARCH_HAS_FEATURE__)
#  if __CUDA_ARCH_HAS_FEATURE__(SM103_ALL)
#    define HAS_TCG 1
#  endif
#endif
#ifndef HAS_TCG
#  if defined(__CUDA_ARCH__) && defined(__CUDA_ARCH_SPECIFIC__)
#    define HAS_TCG 1
#  endif
#endif
#ifndef HAS_TCG
#  define HAS_TCG 0
#endif

#define Bq  32
#define Lq  512
#define Dq  4096
#define Hq  32
#define HDq 128
#define BLq (Bq*Lq)
#define BHq (Bq*Hq)

#define TKH   64
#define NKT16 (Dq/TKH)          // 64
#define A_TB  (128*TKH*2)       // 16384
#define B_TB  (256*TKH*2)       // 32768
#define STG_B (2*A_TB + B_TB)   // 65536
#define NST   3
#define GEMM_SMEM (2048 + NST*STG_B)   // 198656
#define IDESC_F16 0x8400010u    // M=128 N=256
#define IDESC_FA  0x8200010u    // M=128 N=128
// (1/sqrt(128)) * log2(e): fold softmax scale AND exp->ex2 conversion into Q
#define QSCALE2 0.1275174284f

__device__ __half g_A16 [(size_t)BLq*Dq];
__device__ __half g_W16 [4][(size_t)Dq*Dq];
__device__ __half g_AO16[(size_t)BLq*Dq];
__device__ __half g_qh  [(size_t)BHq*Lq*HDq];  // Q tiles (bh,mblk), pre-scaled
__device__ __half g_kh  [(size_t)BHq*Lq*HDq];  // K tiles (bh,jblk)
__device__ __half g_vh  [(size_t)BHq*Lq*HDq];  // V row-major [b,h,l,hd]
__device__ __half g_vt  [(size_t)BHq*Lq*HDq];  // V^T tiles (bh,jblk)

__device__ __forceinline__ uint32_t swz(uint32_t off) { return off ^ ((off >> 3) & 0x70); }
__device__ __forceinline__ uint32_t smem_u32(const void* p) {
    uint32_t a;
    asm("{ .reg .u64 t; cvta.to.shared.u64 t, %1; cvt.u32.u64 %0, t; }" : "=r"(a) : "l"(p));
    return a;
}
__device__ __forceinline__ uint32_t h2u(float a, float b) {
    __half2 h = __floats2half2_rn(a, b);
    return *reinterpret_cast<uint32_t*>(&h);
}

// ==========================================================================
// prepass: fp32 -> fp16 + tile + SW128 swizzle
// ==========================================================================
__global__ void prep_x16(const float4* __restrict__ src) {
    const size_t gid = (size_t)blockIdx.x * blockDim.x + threadIdx.x;
    const size_t i = gid * 8;
    const int m = (int)(i >> 12), k = (int)(i & 4095);
    const int mb = m >> 7, r = m & 127, kt = k >> 6, c = k & 63;
    float4 u = src[2 * gid], v = src[2 * gid + 1];
    uint4 o;
    o.x = h2u(u.x, u.y); o.y = h2u(u.z, u.w);
    o.z = h2u(v.x, v.y); o.w = h2u(v.z, v.w);
    char* tb = (char*)g_A16 + (size_t)(mb * NKT16 + kt) * A_TB;
    *reinterpret_cast<uint4*>(tb + swz((uint32_t)(r * 128 + c * 2))) = o;
}
__global__ void prep_w16(const float4* __restrict__ w0, const float4* __restrict__ w1,
                         const float4* __restrict__ w2, const float4* __restrict__ w3) {
    const int which = blockIdx.y;
    const float4* src = (which == 0) ? w0 : (which == 1) ? w1 : (which == 2) ? w2 : w3;
    const size_t gid = (size_t)blockIdx.x * blockDim.x + threadIdx.x;
    const size_t i = gid * 8;
    const int n = (int)(i >> 12), k = (int)(i & 4095);
    const int nb = n >> 8, r = n & 255, kt = k >> 6, c = k & 63;
    float4 u = src[2 * gid], v = src[2 * gid + 1];
    uint4 o;
    o.x = h2u(u.x, u.y); o.y = h2u(u.z, u.w);
    o.z = h2u(v.x, v.y); o.w = h2u(v.z, v.w);
    char* tb = (char*)g_W16[which] + (size_t)(nb * NKT16 + kt) * B_TB;
    *reinterpret_cast<uint4*>(tb + swz((uint32_t)(r * 128 + c * 2))) = o;
}

// ==========================================================================
#if HAS_TCG
#define MBARRIER_INIT(a, n) \
    asm volatile("mbarrier.init.shared.b64 [%0], %1;" :: "r"((uint32_t)(a)), "r"((uint32_t)(n)) : "memory")
#define MBARRIER_EXPECT_TX(a, b) \
    asm volatile("mbarrier.arrive.expect_tx.shared.b64 _, [%0], %1;" :: "r"((uint32_t)(a)), "r"((uint32_t)(b)) : "memory")
#define MBARRIER_ARRIVE(a) \
    asm volatile("mbarrier.arrive.shared.b64 _, [%0];" :: "r"((uint32_t)(a)) : "memory")
#define MBARRIER_WAIT_PARITY(a, ph) do { \
    asm volatile("{\n\t.reg .pred P1;\n\t" \
        "WAIT_LOOP_%=:\n\t" \
        "mbarrier.try_wait.parity.acquire.cta.shared::cta.b64 P1, [%0], %1, 0x989680;\n\t" \
        "@P1 bra.uni WAIT_DONE_%=;\n\t" \
        "bra.uni WAIT_LOOP_%=;\n\t" \
        "WAIT_DONE_%=:\n\t}" \
        :: "r"((uint32_t)(a)), "r"((uint32_t)(ph)) : "memory"); \
} while (0)
#define TCGEN05_ALLOC(sa, n) \
    asm volatile("tcgen05.alloc.cta_group::1.sync.aligned.shared::cta.b32 [%0], %1;" \
        :: "r"((uint32_t)(sa)), "r"((uint32_t)(n)) : "memory")
#define TCGEN05_DEALLOC(t, n) \
    asm volatile("tcgen05.dealloc.cta_group::1.sync.aligned.b32 %0, %1;" :: "r"(t), "r"((uint32_t)(n)))
#define TCGEN05_RELINQ() \
    asm volatile("tcgen05.relinquish_alloc_permit.cta_group::1.sync.aligned;")
#define TCGEN05_COMMIT(mb) \
    asm volatile("tcgen05.commit.cta_group::1.mbarrier::arrive::one.shared::cluster.b64 [%0];" \
        :: "r"((uint32_t)(mb)) : "memory")
#define TCGEN05_COMMIT_MC(mb, mask) \
    asm volatile("tcgen05.commit.cta_group::1.mbarrier::arrive::one.shared::cluster.multicast::cluster.b64 [%0], %1;" \
        :: "r"((uint32_t)(mb)), "h"((uint16_t)(mask)) : "memory")
#define TCGEN05_FENCE_AFTER()  asm volatile("tcgen05.fence::after_thread_sync;" ::: "memory")
#define TCGEN05_WAIT_LD()      asm volatile("tcgen05.wait::ld.sync.aligned;" ::: "memory")
#define FENCE_PROXY_ASYNC()    asm volatile("fence.proxy.async.shared::cta;" ::: "memory")
#define BAR_CMP()              asm volatile("bar.sync 1, 256;" ::: "memory")
#define CLUSTER_SYNC() do { \
    asm volatile("barrier.cluster.arrive.aligned;" ::: "memory"); \
    asm volatile("barrier.cluster.wait.aligned;"   ::: "memory"); \
} while (0)
#define TCGEN05_LD_X32(r, ta) \
    asm volatile("tcgen05.ld.sync.aligned.32x32b.x32.b32 " \
        "{%0,%1,%2,%3,%4,%5,%6,%7,%8,%9,%10,%11,%12,%13,%14,%15," \
        "%16,%17,%18,%19,%20,%21,%22,%23,%24,%25,%26,%27,%28,%29,%30,%31}, [%32];" \
        : "=r"((r)[0]),"=r"((r)[1]),"=r"((r)[2]),"=r"((r)[3]),"=r"((r)[4]),"=r"((r)[5]),"=r"((r)[6]),"=r"((r)[7]), \
          "=r"((r)[8]),"=r"((r)[9]),"=r"((r)[10]),"=r"((r)[11]),"=r"((r)[12]),"=r"((r)[13]),"=r"((r)[14]),"=r"((r)[15]), \
          "=r"((r)[16]),"=r"((r)[17]),"=r"((r)[18]),"=r"((r)[19]),"=r"((r)[20]),"=r"((r)[21]),"=r"((r)[22]),"=r"((r)[23]), \
          "=r"((r)[24]),"=r"((r)[25]),"=r"((r)[26]),"=r"((r)[27]),"=r"((r)[28]),"=r"((r)[29]),"=r"((r)[30]),"=r"((r)[31]) \
        : "r"(ta))

__device__ __forceinline__ uint32_t elect_one_pred() {
    uint32_t p;
    asm volatile("{ .reg .pred p; elect.sync _|p, 0xFFFFFFFF; selp.b32 %0, 1, 0, p; }" : "=r"(p));
    return p;
}
__device__ __forceinline__ uint32_t cluster_rank() {
    uint32_t r;
    asm("mov.u32 %0, %%cluster_ctarank;" : "=r"(r));
    return r;
}
__device__ __forceinline__ uint64_t mk_desc(uint32_t addr) {
    const uint64_t base = (uint64_t(2) << 61) | (uint64_t(1) << 46) | (uint64_t(64) << 32) | (uint64_t(1) << 16);
    return base | ((uint64_t)(addr >> 4) & 0x3FFF);
}
__device__ __forceinline__ void mma_f16_ss(uint32_t d, uint64_t ad, uint64_t bd,
                                           uint32_t idesc, uint32_t en) {
    asm volatile(
        "{\n\t.reg .pred p;\n\tsetp.ne.u32 p, %4, 0;\n\t"
        "tcgen05.mma.cta_group::1.kind::f16 [%0], %1, %2, %3, {%5,%5,%5,%5}, p;\n\t}"
        :: "r"(d), "l"(ad), "l"(bd), "r"(idesc), "r"(en), "r"(0u) : "memory");
}
__device__ __forceinline__ void bulk_g2s(uint32_t dst, const void* src, uint32_t bytes, uint32_t mbar) {
    asm volatile(
        "cp.async.bulk.shared::cluster.global.mbarrier::complete_tx::bytes [%0], [%1], %2, [%3];"
        :: "r"(dst), "l"(src), "r"(bytes), "r"(mbar) : "memory");
}
// 2D tensor-TMA multicast load (x always 0; y selects the 256B row)
__device__ __forceinline__ void tma2d_mc(uint32_t dst, const CUtensorMap* m, int y,
                                         uint32_t mbar, uint16_t mask) {
    asm volatile(
        "cp.async.bulk.tensor.2d.shared::cluster.global.tile.mbarrier::complete_tx::bytes.multicast::cluster "
        "[%0], [%1, {%2, %3}], [%4], %5;"
        :: "r"(dst), "l"(m), "r"(0), "r"(y), "r"(mbar), "h"(mask) : "memory");
}
// issue 128x128x128 S or PV as 8 K=16 MMAs from two 16KB SW128 sub-tiles
__device__ __forceinline__ void fa_mma8(uint32_t d, uint32_t aoff, uint32_t boff, uint32_t en0) {
#pragma unroll
    for (int c = 0; c < 8; c++) {
        const uint64_t ad = mk_desc(aoff + (c >> 2) * 16384) + 2 * (c & 3);
        const uint64_t bd = mk_desc(boff + (c >> 2) * 16384) + 2 * (c & 3);
        mma_f16_ss(d, ad, bd, IDESC_FA, (c > 0) ? 1u : en0);
    }
}
#endif  // HAS_TCG

// ==========================================================================
// tcgen05 fp16 GEMM, cluster-4 tensor-TMA multicast, 256x256 tiles/CTA
// (512x512 per cluster). mode 0: fused QKV; mode 1: out projection.
// Rank r: mi=r&1, ni=r>>1. r<2 produce A(mi) -> masks {0x5,0xA};
// r>=2 produce B(nsuper*2 + r-2) -> masks {0x3,0xC}.
// ==========================================================================
__global__ __launch_bounds__(128, 1) __cluster_dims__(4, 1, 1)
void gemm_tc(const __grid_constant__ CUtensorMap mA,
             const __grid_constant__ CUtensorMap mB0,
             const __grid_constant__ CUtensorMap mB1,
             const __grid_constant__ CUtensorMap mB2,
             const float* __restrict__ b0p, const float* __restrict__ b1p,
             const float* __restrict__ b2p, float* __restrict__ outp, int mode) {
#if HAS_TCG
    extern __shared__ char smem[];
    const uint32_t sbase = smem_u32(smem);
    const uint32_t mb0   = sbase + 8;
    const uint32_t done  = sbase + 8 + 16 * NST;
    const uint32_t stg0  = (sbase + 128 + 1023) & ~1023u;

    const int tid = threadIdx.x, wid = tid >> 5, lane = tid & 31;
    const uint32_t r = cluster_rank();

    int which, msuper, nsuper;
    const float* bias;
    if (mode == 0) {
        which = blockIdx.y >> 8;
        const int rem = blockIdx.y & 255;
        msuper = rem >> 3; nsuper = rem & 7;
        bias = (which == 0) ? b0p : (which == 1) ? b1p : b2p;
    } else {
        which = 3;
        msuper = blockIdx.y >> 3; nsuper = blockIdx.y & 7;
        bias = b0p;
    }
    const CUtensorMap* mB = (which == 0 || which == 3) ? &mB0 : (which == 1) ? &mB1 : &mB2;
    const int my   = msuper * 2 + (int)(r & 1);     // 256-row block 0..63
    const int nblk = nsuper * 2 + (int)(r >> 1);    // 256-col block 0..15
    const int n0 = nblk * 256;

    if (wid == 0) TCGEN05_ALLOC(sbase, 512);
    if (tid == 0) {
#pragma unroll
        for (int s = 0; s < NST; s++) {
            MBARRIER_INIT(mb0 + 16 * s, 1);       // full: 1 expect_tx arrive
            MBARRIER_INIT(mb0 + 16 * s + 8, 2);   // empty: 2 consumer commits
        }
        MBARRIER_INIT(done, 1);
#pragma unroll
        for (int s = 0; s < NST; s++) MBARRIER_EXPECT_TX(mb0 + 16 * s, STG_B);  // arm phase 0
    }
    __syncthreads();
    CLUSTER_SYNC();   // barriers armed cluster-wide before any TMA/commit

    uint32_t tmem;
    asm volatile("ld.shared.b32 %0, [%1];" : "=r"(tmem) : "r"(sbase));

    // consumer commit mask: my A producer (rank mi) + my B producer (rank 2+ni)
    const uint16_t cmask = (uint16_t)((1u << (r & 1)) | (1u << (2 + (r >> 1))));

    if (tid == 96) {
        // ---- producer: one tile type, multicast x2 ----
        const uint16_t amask = (r == 0) ? 0x5 : 0xA;
        const uint16_t bmask = (r == 2) ? 0x3 : 0xC;
        const int nblk_p = nsuper * 2 + (int)r - 2;   // valid for r>=2
        int s = 0, ph = 1;
        for (int kt = 0; kt < NKT16; ++kt) {
            MBARRIER_WAIT_PARITY(mb0 + 16 * s + 8, ph);
            const uint32_t st = stg0 + s * STG_B;
            if (r < 2) {
                const int y0 = (128 * my + kt) * 64;
                tma2d_mc(st,        &mA, y0,        mb0 + 16 * s, amask);
                tma2d_mc(st + A_TB, &mA, y0 + 4096, mb0 + 16 * s, amask);
            } else {
                const int yb = (nblk_p * 64 + kt) * 128;
                tma2d_mc(st + 2 * A_TB, mB, yb, mb0 + 16 * s, bmask);
            }
            if (++s == NST) { s = 0; ph ^= 1; }
        }
    } else if (wid == 0) {
        if (elect_one_pred()) {
            int s = 0, ph = 0;
            uint32_t en = 0;
            for (int kt = 0; kt < NKT16; ++kt) {
                MBARRIER_WAIT_PARITY(mb0 + 16 * s, ph);
                MBARRIER_EXPECT_TX(mb0 + 16 * s, STG_B);   // arm next phase BEFORE freeing
                const uint32_t st = stg0 + s * STG_B;
                const uint64_t a0 = mk_desc(st);
                const uint64_t a1 = mk_desc(st + A_TB);
                const uint64_t bd = mk_desc(st + 2 * A_TB);
#pragma unroll
                for (int c = 0; c < 4; c++) {
                    mma_f16_ss(tmem,       a0 + 2 * c, bd + 2 * c, IDESC_F16, en);
                    mma_f16_ss(tmem + 256, a1 + 2 * c, bd + 2 * c, IDESC_F16, en);
                    en = 1;
                }
                TCGEN05_COMMIT_MC(mb0 + 16 * s + 8, cmask);   // free stage at both producers
                if (++s == NST) { s = 0; ph ^= 1; }
            }
            TCGEN05_COMMIT(done);
        }
    }

    MBARRIER_WAIT_PARITY(done, 0);
    TCGEN05_FENCE_AFTER();

#pragma unroll
    for (int dt = 0; dt < 2; dt++) {
        const int m = (2 * my + dt) * 128 + wid * 32 + lane;
        const int b = m >> 9, l = m & 511;
#pragma unroll
        for (int ch = 0; ch < 8; ch++) {
            uint32_t rr[32];
            TCGEN05_LD_X32(rr, tmem + dt * 256 + ch * 32);
            TCGEN05_WAIT_LD();
            const int cb = n0 + ch * 32;
            if (which == 2) {
                const int h = cb >> 7;
                const size_t rowbase = (((size_t)b * Hq + h) * Lq + l) * HDq;
#pragma unroll
                for (int j = 0; j < 32; j += 2) {
                    const int col = cb + j;
                    *reinterpret_cast<__half2*>(&g_vh[rowbase + (col & 127)]) =
                        __floats2half2_rn(__uint_as_float(rr[j])     + bias[col],
                                          __uint_as_float(rr[j + 1]) + bias[col + 1]);
                }
            } else if (which < 2) {
                char* dst = (char*)((which == 0) ? g_qh : g_kh);
                const int h = cb >> 7;
                const int bh = b * Hq + h;
                const int mblk = l >> 7, trow = l & 127;
#pragma unroll
                for (int j = 0; j < 32; j += 2) {
                    const int col = cb + j;
                    float v0 = __uint_as_float(rr[j])     + bias[col];
                    float v1 = __uint_as_float(rr[j + 1]) + bias[col + 1];
                    if (which == 0) { v0 *= QSCALE2; v1 *= QSCALE2; }
                    const int hd = col & 127, kt = hd >> 6, tc = hd & 63;
                    const size_t base = ((size_t)((bh * 4 + mblk) * 2 + kt)) * 16384;
                    *reinterpret_cast<uint32_t*>(dst + base + swz((uint32_t)(trow * 128 + tc * 2)))
                        = h2u(v0, v1);
                }
            } else {
#pragma unroll
                for (int j = 0; j < 32; j += 2) {
                    const int col = cb + j;
                    float2 v;
                    v.x = __uint_as_float(rr[j])     + bias[col];
                    v.y = __uint_as_float(rr[j + 1]) + bias[col + 1];
                    *reinterpret_cast<float2*>(&outp[(size_t)m * Dq + col]) = v;
                }
            }
        }
    }

    __syncthreads();
    CLUSTER_SYNC();
    if (wid == 0) {
        TCGEN05_RELINQ();
        TCGEN05_DEALLOC(tmem, 512);
    }
#endif  // HAS_TCG
}

// ==========================================================================
// V transpose -> V^T SW128 tiles. 64x64 blocks, fully vectorized 16B I/O.
// ==========================================================================
__global__ void vt_k() {
    __shared__ __half t[64][72];
    const int bh = blockIdx.z;
    const int l0 = blockIdx.x * 64, d0 = blockIdx.y * 64;
    const int tid = threadIdx.x;
    const __half* src = g_vh + (size_t)bh * Lq * HDq;
#pragma unroll
    for (int i = 0; i < 2; i++) {
        const int u = tid + i * 256;
        const int l = u >> 3, c8 = u & 7;
        const uint4 v = *reinterpret_cast<const uint4*>(&src[(size_t)(l0 + l) * HDq + d0 + c8 * 8]);
        *reinterpret_cast<uint4*>(&t[l][c8 * 8]) = v;
    }
    __syncthreads();
    const int lblk = blockIdx.x;
    const int jblk = lblk >> 1, lt = lblk & 1;
    char* tb = (char*)g_vt + ((size_t)((bh * 4 + jblk) * 2 + lt)) * 16384;
#pragma unroll
    for (int i = 0; i < 2; i++) {
        const int u = tid + i * 256;
        const int d = u & 63, c8 = u >> 6;
        __half h[8];
#pragma unroll
        for (int j = 0; j < 8; j++) h[j] = t[c8 * 8 + j][d];
        const uint32_t off = swz((uint32_t)((d0 + d) * 128 + c8 * 16));
        *reinterpret_cast<uint4*>(tb + off) = *reinterpret_cast<uint4*>(h);
    }
}

// ==========================================================================
// tcgen05 flash attention v3 (unchanged from R13): one CTA per bh,
// mb looped 0..3, O ping-pong. 288 threads.
// TMEM: O0 @0, O1 @128, S0 @256, S1 @384.
// ==========================================================================
__global__ __launch_bounds__(288, 1) void fa_k() {
#if HAS_TCG
    extern __shared__ char smem[];
    const uint32_t sb = smem_u32(smem);
    const uint32_t qful = sb + 16, qfree = sb + 24;
    const uint32_t kvfl[2] = {sb + 32, sb + 40};
    const uint32_t kvfr[2] = {sb + 48, sb + 56};
    const uint32_t sful[2] = {sb + 64, sb + 72};
    const uint32_t sdon[2] = {sb + 80, sb + 88};
    const uint32_t pready = sb + 96, pvdone = sb + 104;
    const uint32_t odon[2]   = {sb + 112, sb + 120};
    const uint32_t oefree[2] = {sb + 128, sb + 136};
    const uint32_t stg0 = (sb + 256 + 1023) & ~1023u;
    const uint32_t qoff = stg0, kvoff = stg0 + 32768, poff = stg0 + 163840;
    char* const psm = smem + (poff - sb);

    const int tid = threadIdx.x, w = tid >> 5, lane = tid & 31;
    const int bh = blockIdx.x;

    if (w == 0) TCGEN05_ALLOC(sb, 512);
    if (tid == 0) {
        MBARRIER_INIT(qful, 1);  MBARRIER_INIT(qfree, 1);
#pragma unroll
        for (int s = 0; s < 2; s++) {
            MBARRIER_INIT(kvfl[s], 1);  MBARRIER_INIT(kvfr[s], 1);
            MBARRIER_INIT(sful[s], 1);  MBARRIER_INIT(sdon[s], 256);
            MBARRIER_INIT(odon[s], 1);  MBARRIER_INIT(oefree[s], 256);
        }
        MBARRIER_INIT(pready, 256);
        MBARRIER_INIT(pvdone, 1);
    }
    __syncthreads();

    uint32_t tmem;
    asm volatile("ld.shared.b32 %0, [%1];" : "=r"(tmem) : "r"(sb));

    const char* Qb = (const char*)g_qh + (size_t)bh * 4 * 32768;
    const char* Kt = (const char*)g_kh + (size_t)bh * 4 * 32768;
    const char* Vt = (const char*)g_vt + (size_t)bh * 4 * 32768;

    if (tid == 256) {
        MBARRIER_EXPECT_TX(qful, 32768);
        bulk_g2s(qoff, Qb, 32768, qful);
        int qfph = 0, frph[2] = {0, 0}, k = 0;
        for (int mb = 0; mb < 4; mb++) {
            for (int jb = 0; jb <= mb; jb++) {
                const int s = k & 1;
                if (k >= 2) { MBARRIER_WAIT_PARITY(kvfr[s], frph[s]); frph[s] ^= 1; }
                MBARRIER_EXPECT_TX(kvfl[s], 65536);
                bulk_g2s(kvoff + s * 65536,         Kt + (size_t)jb * 32768, 32768, kvfl[s]);
                bulk_g2s(kvoff + s * 65536 + 32768, Vt + (size_t)jb * 32768, 32768, kvfl[s]);
                k++;
            }
            if (mb < 3) {
                MBARRIER_WAIT_PARITY(qfree, qfph & 1); qfph++;
                MBARRIER_EXPECT_TX(qful, 32768);
                bulk_g2s(qoff, Qb + (size_t)(mb + 1) * 32768, 32768, qful);
            }
        }
    } else if (tid == 257) {
        const int MB[10] = {0,1,1,2,2,2,3,3,3,3};
        const int JB[10] = {0,0,1,0,1,2,0,1,2,3};
        int qph = 0, kvph[2] = {0,0}, sdph[2] = {0,0}, prph = 0, oeph[2] = {0,0};
        MBARRIER_WAIT_PARITY(qful, 0); qph = 1;
        MBARRIER_WAIT_PARITY(kvfl[0], 0); kvph[0] = 1;
        fa_mma8(tmem + 256, qoff, kvoff, 0);
        TCGEN05_COMMIT(sful[0]);
        TCGEN05_COMMIT(qfree);
        for (int k = 0; k < 10; k++) {
            const int mb = MB[k], jb = JB[k], s = k & 1, ob = mb & 1;
            const bool have_next = (k < 9);
            const bool next_new_q = have_next && (JB[k + 1] == 0);
            if (have_next && !next_new_q) {
                const int s2 = (k + 1) & 1;
                MBARRIER_WAIT_PARITY(kvfl[s2], kvph[s2]); kvph[s2] ^= 1;
                if (k + 1 >= 2) { MBARRIER_WAIT_PARITY(sdon[s2], sdph[s2]); sdph[s2] ^= 1; }
                fa_mma8(tmem + 256 + s2 * 128, qoff, kvoff + s2 * 65536, 0);
                TCGEN05_COMMIT(sful[s2]);
                if (JB[k + 1] == MB[k + 1]) TCGEN05_COMMIT(qfree);
            }
            MBARRIER_WAIT_PARITY(pready, prph & 1); prph++;
            if (jb == 0 && mb >= 2) { MBARRIER_WAIT_PARITY(oefree[ob], oeph[ob]); oeph[ob] ^= 1; }
            fa_mma8(tmem + ob * 128, poff, kvoff + s * 65536 + 32768, (jb > 0) ? 1u : 0u);
            TCGEN05_COMMIT(kvfr[s]);
            TCGEN05_COMMIT(pvdone);
            if (jb == mb) TCGEN05_COMMIT(odon[ob]);
            if (have_next && next_new_q) {
                const int s2 = (k + 1) & 1;
                MBARRIER_WAIT_PARITY(qful, qph & 1); qph++;
                MBARRIER_WAIT_PARITY(kvfl[s2], kvph[s2]); kvph[s2] ^= 1;
                if (k + 1 >= 2) { MBARRIER_WAIT_PARITY(sdon[s2], sdph[s2]); sdph[s2] ^= 1; }
                fa_mma8(tmem + 256 + s2 * 128, qoff, kvoff + s2 * 65536, 0);
                TCGEN05_COMMIT(sful[s2]);
                if (JB[k + 1] == MB[k + 1]) TCGEN05_COMMIT(qfree);
            }
        }
    }

    if (tid < 256) {
        int sfph[2] = {0, 0}, pvph = 0, odph[2] = {0, 0};
        const int rl = (w & 3) * 32 + lane;
        const int cb = (w >> 2) * 64;
        int k = 0;
        const int b2 = bh >> 5, h2 = bh & 31;
        char* aob = (char*)g_AO16;
        const int ktc = (h2 * 128 + cb) >> 6;
        for (int mb = 0; mb < 4; mb++) {
            float lrow = 0.f;
            const int ob = mb & 1;
            for (int jb = 0; jb <= mb; jb++) {
                const int s = k & 1;
                MBARRIER_WAIT_PARITY(sful[s], sfph[s]); sfph[s] ^= 1;
                TCGEN05_FENCE_AFTER();
                uint32_t r[64];
                TCGEN05_LD_X32(r,      tmem + 256 + s * 128 + cb);
                TCGEN05_LD_X32(r + 32, tmem + 256 + s * 128 + cb + 32);
                TCGEN05_WAIT_LD();
                MBARRIER_ARRIVE(sdon[s]);
                if (k > 0) { MBARRIER_WAIT_PARITY(pvdone, pvph & 1); pvph++; }
                const bool diag = (jb == mb);
#pragma unroll
                for (int c = 0; c < 64; c += 8) {
                    float p[8];
#pragma unroll
                    for (int j = 0; j < 8; j++) {
                        float e;
                        asm("ex2.approx.f32 %0, %1;" : "=f"(e) : "f"(__uint_as_float(r[c + j])));
                        p[j] = (diag && (cb + c + j) > rl) ? 0.f : e;
                        lrow += p[j];
                    }
                    uint4 o;
                    o.x = h2u(p[0], p[1]); o.y = h2u(p[2], p[3]);
                    o.z = h2u(p[4], p[5]); o.w = h2u(p[6], p[7]);
                    const uint32_t off = (uint32_t)((cb >> 6) * 16384)
                                         + swz((uint32_t)(rl * 128 + c * 2));
                    *reinterpret_cast<uint4*>(psm + off) = o;
                }
                FENCE_PROXY_ASYNC();
                MBARRIER_ARRIVE(pready);
                k++;
            }
            MBARRIER_WAIT_PARITY(odon[ob], odph[ob]); odph[ob] ^= 1;
            TCGEN05_FENCE_AFTER();
            *reinterpret_cast<float*>(psm + ((cb >> 6) * 128 + rl) * 4) = lrow;
            BAR_CMP();
            const float ltot = *reinterpret_cast<float*>(psm + rl * 4)
                             + *reinterpret_cast<float*>(psm + (128 + rl) * 4);
            BAR_CMP();
            uint32_t r[64];
            TCGEN05_LD_X32(r,      tmem + ob * 128 + cb);
            TCGEN05_LD_X32(r + 32, tmem + ob * 128 + cb + 32);
            TCGEN05_WAIT_LD();
            const float inv = 1.f / ltot;
            const int R = b2 * Lq + mb * 128 + rl;
            const int mb2 = R >> 7, rrow = R & 127;
#pragma unroll
            for (int c = 0; c < 64; c += 8) {
                uint4 o;
                o.x = h2u(__uint_as_float(r[c])     * inv, __uint_as_float(r[c + 1]) * inv);
                o.y = h2u(__uint_as_float(r[c + 2]) * inv, __uint_as_float(r[c + 3]) * inv);
                o.z = h2u(__uint_as_float(r[c + 4]) * inv, __uint_as_float(r[c + 5]) * inv);
                o.w = h2u(__uint_as_float(r[c + 6]) * inv, __uint_as_float(r[c + 7]) * inv);
                *reinterpret_cast<uint4*>(aob + ((size_t)(mb2 * NKT16 + ktc)) * A_TB
                                              + swz((uint32_t)(rrow * 128 + c * 2))) = o;
            }
            MBARRIER_ARRIVE(oefree[ob]);
        }
    }

    __syncthreads();
    if (w == 0) {
        TCGEN05_RELINQ();
        TCGEN05_DEALLOC(tmem, 512);
    }
#endif  // HAS_TCG
}

// ==========================================================================
extern "C" void kernel_launch(void* const* d_in, const int* in_sizes, int n_in,
                              void* d_out, int out_size) {
    const float* x  = (const float*)d_in[0];
    const float* Wq = (const float*)d_in[1];
    const float* bq = (const float*)d_in[2];
    const float* Wk = (const float*)d_in[3];
    const float* bk = (const float*)d_in[4];
    const float* Wv = (const float*)d_in[5];
    const float* bv = (const float*)d_in[6];
    const float* Wo = (const float*)d_in[7];
    const float* bo = (const float*)d_in[8];
    float* out = (float*)d_out;

    // ---- one-time: build tensor maps via driver entry point (no -lcuda) ----
    static bool s_init = false;
    static CUtensorMap s_mA, s_mW[4], s_mAO;
    if (!s_init) {
        void* fn = nullptr;
        cudaDriverEntryPointQueryResult qr;
        cudaGetDriverEntryPoint("cuTensorMapEncodeTiled", &fn, cudaEnableDefault, &qr);
        typedef CUresult (*EncT)(CUtensorMap*, CUtensorMapDataType, cuuint32_t, void*,
                                 const cuuint64_t*, const cuuint64_t*, const cuuint32_t*,
                                 const cuuint32_t*, CUtensorMapInterleave, CUtensorMapSwizzle,
                                 CUtensorMapL2promotion, CUtensorMapFloatOOBfill);
        EncT enc = (EncT)fn;
        void *pA = nullptr, *pW = nullptr, *pAO = nullptr;
        cudaGetSymbolAddress(&pA,  g_A16);
        cudaGetSymbolAddress(&pW,  g_W16);
        cudaGetSymbolAddress(&pAO, g_AO16);
        auto mk = [&](CUtensorMap* m, void* base, size_t bytes, uint32_t boxRows) {
            cuuint64_t dims[2] = {256, bytes / 256};
            cuuint64_t strides[1] = {256};
            cuuint32_t box[2] = {256, boxRows};
            cuuint32_t es[2] = {1, 1};
            enc(m, CU_TENSOR_MAP_DATA_TYPE_UINT8, 2, base, dims, strides, box, es,
                CU_TENSOR_MAP_INTERLEAVE_NONE, CU_TENSOR_MAP_SWIZZLE_NONE,
                CU_TENSOR_MAP_L2_PROMOTION_L2_128B, CU_TENSOR_MAP_FLOAT_OOB_FILL_NONE);
        };
        mk(&s_mA, pA, (size_t)BLq * Dq * 2, 64);
        for (int w = 0; w < 4; w++)
            mk(&s_mW[w], (char*)pW + (size_t)w * Dq * Dq * 2, (size_t)Dq * Dq * 2, 128);
        mk(&s_mAO, pAO, (size_t)BLq * Dq * 2, 64);
        s_init = true;
    }

    cudaFuncSetAttribute(gemm_tc, cudaFuncAttributeMaxDynamicSharedMemorySize, GEMM_SMEM);
    cudaFuncSetAttribute(fa_k,    cudaFuncAttributeMaxDynamicSharedMemorySize, GEMM_SMEM);

    // 1) prepass
    prep_x16<<<(int)((size_t)BLq * Dq / 8 / 256), 256>>>((const float4*)x);
    prep_w16<<<dim3((unsigned)((size_t)Dq * Dq / 8 / 256), 4), 256>>>(
        (const float4*)Wq, (const float4*)Wk, (const float4*)Wv, (const float4*)Wo);

    // 2) fused Q/K/V projections: 768 clusters of 4 (which x msuper x nsuper)
    gemm_tc<<<dim3(4, 768), 128, GEMM_SMEM>>>(s_mA, s_mW[0], s_mW[1], s_mW[2],
                                              bq, bk, bv, nullptr, 0);

    // 3) attention
    vt_k<<<dim3(8, 2, BHq), 256>>>();
    fa_k<<<BHq, 288, GEMM_SMEM>>>();

    // 4) output projection: 256 clusters of 4
    gemm_tc<<<dim3(4, 256), 128, GEMM_SMEM>>>(s_mAO, s_mW[3], s_mW[3], s_mW[3],
                                              bo, bo, bo, out, 1);
}

// round 15
// speedup vs baseline: 1.0934x; 1.0934x over previous
#include <cuda_runtime.h>
#include <cuda_fp16.h>
#include <cstdint>

#if defined(__CUDA_ARCH__) && defined(__CUDA_ARCH_HAS_FEATURE__)
#  if __CUDA_ARCH_HAS_FEATURE__(SM103_ALL)
#    define HAS_TCG 1
#  endif
#endif
#ifndef HAS_TCG
#  if defined(__CUDA_ARCH__) && defined(__CUDA_ARCH_SPECIFIC__)
#    define HAS_TCG 1
#  endif
#endif
#ifndef HAS_TCG
#  define HAS_TCG 0
#endif

#define Bq  32
#define Lq  512
#define Dq  4096
#define Hq  32
#define HDq 128
#define BLq (Bq*Lq)
#define BHq (Bq*Hq)

#define TKH   64
#define NKT16 (Dq/TKH)          // 64
#define A_TB  (128*TKH*2)       // 16384
#define B_TB  (256*TKH*2)       // 32768
#define STG_B (2*A_TB + B_TB)
#define NST   3
#define GEMM_SMEM (2048 + NST*STG_B)   // 198656
#define IDESC_F16 0x8400010u    // M=128 N=256
#define IDESC_FA  0x8200010u    // M=128 N=128
// (1/sqrt(128)) * log2(e): fold softmax scale AND exp->ex2 conversion into Q
#define QSCALE2 0.1275174284f

__device__ __half g_A16 [(size_t)BLq*Dq];
__device__ __half g_W16 [4][(size_t)Dq*Dq];
__device__ __half g_AO16[(size_t)BLq*Dq];
__device__ __half g_qh  [(size_t)BHq*Lq*HDq];  // Q tiles (bh,mblk), pre-scaled
__device__ __half g_kh  [(size_t)BHq*Lq*HDq];  // K tiles (bh,jblk)
__device__ __half g_vh  [(size_t)BHq*Lq*HDq];  // V row-major [b,h,l,hd]
__device__ __half g_vt  [(size_t)BHq*Lq*HDq];  // V^T tiles (bh,jblk)

__device__ __forceinline__ uint32_t swz(uint32_t off) { return off ^ ((off >> 3) & 0x70); }
__device__ __forceinline__ uint32_t smem_u32(const void* p) {
    uint32_t a;
    asm("{ .reg .u64 t; cvta.to.shared.u64 t, %1; cvt.u32.u64 %0, t; }" : "=r"(a) : "l"(p));
    return a;
}
__device__ __forceinline__ uint32_t h2u(float a, float b) {
    __half2 h = __floats2half2_rn(a, b);
    return *reinterpret_cast<uint32_t*>(&h);
}

// ==========================================================================
// fused prepass: fp32 -> fp16 + tile + SW128 swizzle.
// blockIdx.y 0..3: weight matrix y (B tiles, 256x64).
// blockIdx.y 4..7: x quarter (y-4)   (A tiles, 128x64).
// ==========================================================================
__global__ void prep_all(const float4* __restrict__ x,
                         const float4* __restrict__ w0, const float4* __restrict__ w1,
                         const float4* __restrict__ w2, const float4* __restrict__ w3) {
    const int yb = blockIdx.y;
    if (yb < 4) {
        const float4* src = (yb == 0) ? w0 : (yb == 1) ? w1 : (yb == 2) ? w2 : w3;
        const size_t gid = (size_t)blockIdx.x * blockDim.x + threadIdx.x;
        const size_t i = gid * 8;
        const int n = (int)(i >> 12), k = (int)(i & 4095);
        const int nb = n >> 8, r = n & 255, kt = k >> 6, c = k & 63;
        float4 u = src[2 * gid], v = src[2 * gid + 1];
        uint4 o;
        o.x = h2u(u.x, u.y); o.y = h2u(u.z, u.w);
        o.z = h2u(v.x, v.y); o.w = h2u(v.z, v.w);
        char* tb = (char*)g_W16[yb] + (size_t)(nb * NKT16 + kt) * B_TB;
        *reinterpret_cast<uint4*>(tb + swz((uint32_t)(r * 128 + c * 2))) = o;
    } else {
        const size_t gid = ((size_t)(yb - 4) * gridDim.x + blockIdx.x) * blockDim.x + threadIdx.x;
        const size_t i = gid * 8;
        const int m = (int)(i >> 12), k = (int)(i & 4095);
        const int mb = m >> 7, r = m & 127, kt = k >> 6, c = k & 63;
        float4 u = x[2 * gid], v = x[2 * gid + 1];
        uint4 o;
        o.x = h2u(u.x, u.y); o.y = h2u(u.z, u.w);
        o.z = h2u(v.x, v.y); o.w = h2u(v.z, v.w);
        char* tb = (char*)g_A16 + (size_t)(mb * NKT16 + kt) * A_TB;
        *reinterpret_cast<uint4*>(tb + swz((uint32_t)(r * 128 + c * 2))) = o;
    }
}

// ==========================================================================
#if HAS_TCG
#define MBARRIER_INIT(a, n) \
    asm volatile("mbarrier.init.shared.b64 [%0], %1;" :: "r"((uint32_t)(a)), "r"((uint32_t)(n)) : "memory")
#define MBARRIER_EXPECT_TX(a, b) \
    asm volatile("mbarrier.arrive.expect_tx.shared.b64 _, [%0], %1;" :: "r"((uint32_t)(a)), "r"((uint32_t)(b)) : "memory")
#define MBARRIER_ARRIVE(a) \
    asm volatile("mbarrier.arrive.shared.b64 _, [%0];" :: "r"((uint32_t)(a)) : "memory")
#define MBARRIER_WAIT_PARITY(a, ph) do { \
    asm volatile("{\n\t.reg .pred P1;\n\t" \
        "WAIT_LOOP_%=:\n\t" \
        "mbarrier.try_wait.parity.acquire.cta.shared::cta.b64 P1, [%0], %1, 0x989680;\n\t" \
        "@P1 bra.uni WAIT_DONE_%=;\n\t" \
        "bra.uni WAIT_LOOP_%=;\n\t" \
        "WAIT_DONE_%=:\n\t}" \
        :: "r"((uint32_t)(a)), "r"((uint32_t)(ph)) : "memory"); \
} while (0)
#define TCGEN05_ALLOC(sa, n) \
    asm volatile("tcgen05.alloc.cta_group::1.sync.aligned.shared::cta.b32 [%0], %1;" \
        :: "r"((uint32_t)(sa)), "r"((uint32_t)(n)) : "memory")
#define TCGEN05_DEALLOC(t, n) \
    asm volatile("tcgen05.dealloc.cta_group::1.sync.aligned.b32 %0, %1;" :: "r"(t), "r"((uint32_t)(n)))
#define TCGEN05_RELINQ() \
    asm volatile("tcgen05.relinquish_alloc_permit.cta_group::1.sync.aligned;")
#define TCGEN05_COMMIT(mb) \
    asm volatile("tcgen05.commit.cta_group::1.mbarrier::arrive::one.shared::cluster.b64 [%0];" \
        :: "r"((uint32_t)(mb)) : "memory")
#define TCGEN05_FENCE_AFTER()  asm volatile("tcgen05.fence::after_thread_sync;" ::: "memory")
#define TCGEN05_WAIT_LD()      asm volatile("tcgen05.wait::ld.sync.aligned;" ::: "memory")
#define FENCE_PROXY_ASYNC()    asm volatile("fence.proxy.async.shared::cta;" ::: "memory")
#define BAR_CMP()              asm volatile("bar.sync 1, 256;" ::: "memory")
#define TCGEN05_LD_X32(r, ta) \
    asm volatile("tcgen05.ld.sync.aligned.32x32b.x32.b32 " \
        "{%0,%1,%2,%3,%4,%5,%6,%7,%8,%9,%10,%11,%12,%13,%14,%15," \
        "%16,%17,%18,%19,%20,%21,%22,%23,%24,%25,%26,%27,%28,%29,%30,%31}, [%32];" \
        : "=r"((r)[0]),"=r"((r)[1]),"=r"((r)[2]),"=r"((r)[3]),"=r"((r)[4]),"=r"((r)[5]),"=r"((r)[6]),"=r"((r)[7]), \
          "=r"((r)[8]),"=r"((r)[9]),"=r"((r)[10]),"=r"((r)[11]),"=r"((r)[12]),"=r"((r)[13]),"=r"((r)[14]),"=r"((r)[15]), \
          "=r"((r)[16]),"=r"((r)[17]),"=r"((r)[18]),"=r"((r)[19]),"=r"((r)[20]),"=r"((r)[21]),"=r"((r)[22]),"=r"((r)[23]), \
          "=r"((r)[24]),"=r"((r)[25]),"=r"((r)[26]),"=r"((r)[27]),"=r"((r)[28]),"=r"((r)[29]),"=r"((r)[30]),"=r"((r)[31]) \
        : "r"(ta))

__device__ __forceinline__ uint32_t elect_one_pred() {
    uint32_t p;
    asm volatile("{ .reg .pred p; elect.sync _|p, 0xFFFFFFFF; selp.b32 %0, 1, 0, p; }" : "=r"(p));
    return p;
}
__device__ __forceinline__ uint64_t mk_desc(uint32_t addr) {
    const uint64_t base = (uint64_t(2) << 61) | (uint64_t(1) << 46) | (uint64_t(64) << 32) | (uint64_t(1) << 16);
    return base | ((uint64_t)(addr >> 4) & 0x3FFF);
}
__device__ __forceinline__ void mma_f16_ss(uint32_t d, uint64_t ad, uint64_t bd,
                                           uint32_t idesc, uint32_t en) {
    asm volatile(
        "{\n\t.reg .pred p;\n\tsetp.ne.u32 p, %4, 0;\n\t"
        "tcgen05.mma.cta_group::1.kind::f16 [%0], %1, %2, %3, {%5,%5,%5,%5}, p;\n\t}"
        :: "r"(d), "l"(ad), "l"(bd), "r"(idesc), "r"(en), "r"(0u) : "memory");
}
__device__ __forceinline__ void bulk_g2s(uint32_t dst, const void* src, uint32_t bytes, uint32_t mbar) {
    asm volatile(
        "cp.async.bulk.shared::cluster.global.mbarrier::complete_tx::bytes [%0], [%1], %2, [%3];"
        :: "r"(dst), "l"(src), "r"(bytes), "r"(mbar) : "memory");
}
// issue 128x128x128 S or PV as 8 K=16 MMAs from two 16KB SW128 sub-tiles
__device__ __forceinline__ void fa_mma8(uint32_t d, uint32_t aoff, uint32_t boff, uint32_t en0) {
#pragma unroll
    for (int c = 0; c < 8; c++) {
        const uint64_t ad = mk_desc(aoff + (c >> 2) * 16384) + 2 * (c & 3);
        const uint64_t bd = mk_desc(boff + (c >> 2) * 16384) + 2 * (c & 3);
        mma_f16_ss(d, ad, bd, IDESC_FA, (c > 0) ? 1u : en0);
    }
}
#endif  // HAS_TCG

// ==========================================================================
// tcgen05 fp16 GEMM, 256x256 tiles (R13 exact). mode 0: fused QKV; 1: out.
// ==========================================================================
__global__ __launch_bounds__(128, 1) void gemm_tc(const float* __restrict__ b0p,
                                                  const float* __restrict__ b1p,
                                                  const float* __restrict__ b2p,
                                                  float* __restrict__ outp, int mode) {
#if HAS_TCG
    extern __shared__ char smem[];
    const uint32_t sbase = smem_u32(smem);
    const uint32_t mb0   = sbase + 8;
    const uint32_t done  = sbase + 8 + 16 * NST;
    const uint32_t stg0  = (sbase + 128 + 1023) & ~1023u;

    const int tid = threadIdx.x, wid = tid >> 5, lane = tid & 31;
    const int n0 = blockIdx.x * 256;

    int which, my;
    const float* bias;
    if (mode == 0) {
        which = blockIdx.y >> 6;
        my    = blockIdx.y & 63;
        bias  = (which == 0) ? b0p : (which == 1) ? b1p : b2p;
    } else {
        which = 3; my = blockIdx.y; bias = b0p;
    }

    if (wid == 0) TCGEN05_ALLOC(sbase, 512);
    if (tid == 0) {
#pragma unroll
        for (int s = 0; s < NST; s++) {
            MBARRIER_INIT(mb0 + 16 * s, 1);
            MBARRIER_INIT(mb0 + 16 * s + 8, 1);
        }
        MBARRIER_INIT(done, 1);
    }
    __syncthreads();

    uint32_t tmem;
    asm volatile("ld.shared.b32 %0, [%1];" : "=r"(tmem) : "r"(sbase));

    const char* Abase = (const char*)(which < 3 ? g_A16 : g_AO16);
    const char* At0 = Abase + (size_t)(2 * my)     * NKT16 * A_TB;
    const char* At1 = Abase + (size_t)(2 * my + 1) * NKT16 * A_TB;
    const char* Bt  = (const char*)g_W16[which] + (size_t)blockIdx.x * NKT16 * B_TB;

    if (tid == 96) {
        int s = 0, ph = 1;
        for (int kt = 0; kt < NKT16; ++kt) {
            MBARRIER_WAIT_PARITY(mb0 + 16 * s + 8, ph);
            MBARRIER_EXPECT_TX(mb0 + 16 * s, STG_B);
            const uint32_t st = stg0 + s * STG_B;
            bulk_g2s(st,            At0 + (size_t)kt * A_TB, A_TB, mb0 + 16 * s);
            bulk_g2s(st + A_TB,     At1 + (size_t)kt * A_TB, A_TB, mb0 + 16 * s);
            bulk_g2s(st + 2 * A_TB, Bt  + (size_t)kt * B_TB, B_TB, mb0 + 16 * s);
            if (++s == NST) { s = 0; ph ^= 1; }
        }
    } else if (wid == 0) {
        if (elect_one_pred()) {
            int s = 0, ph = 0;
            uint32_t en = 0;
            for (int kt = 0; kt < NKT16; ++kt) {
                MBARRIER_WAIT_PARITY(mb0 + 16 * s, ph);
                const uint32_t st = stg0 + s * STG_B;
                const uint64_t a0 = mk_desc(st);
                const uint64_t a1 = mk_desc(st + A_TB);
                const uint64_t bd = mk_desc(st + 2 * A_TB);
#pragma unroll
                for (int c = 0; c < 4; c++) {
                    mma_f16_ss(tmem,       a0 + 2 * c, bd + 2 * c, IDESC_F16, en);
                    mma_f16_ss(tmem + 256, a1 + 2 * c, bd + 2 * c, IDESC_F16, en);
                    en = 1;
                }
                TCGEN05_COMMIT(mb0 + 16 * s + 8);
                if (++s == NST) { s = 0; ph ^= 1; }
            }
            TCGEN05_COMMIT(done);
        }
    }

    MBARRIER_WAIT_PARITY(done, 0);
    TCGEN05_FENCE_AFTER();

#pragma unroll
    for (int dt = 0; dt < 2; dt++) {
        const int m = (2 * my + dt) * 128 + wid * 32 + lane;
        const int b = m >> 9, l = m & 511;
#pragma unroll
        for (int ch = 0; ch < 8; ch++) {
            uint32_t rr[32];
            TCGEN05_LD_X32(rr, tmem + dt * 256 + ch * 32);
            TCGEN05_WAIT_LD();
            const int cb = n0 + ch * 32;
            if (which == 2) {
                const int h = cb >> 7;
                const size_t rowbase = (((size_t)b * Hq + h) * Lq + l) * HDq;
#pragma unroll
                for (int j = 0; j < 32; j += 2) {
                    const int col = cb + j;
                    *reinterpret_cast<__half2*>(&g_vh[rowbase + (col & 127)]) =
                        __floats2half2_rn(__uint_as_float(rr[j])     + bias[col],
                                          __uint_as_float(rr[j + 1]) + bias[col + 1]);
                }
            } else if (which < 2) {
                char* dst = (char*)((which == 0) ? g_qh : g_kh);
                const int h = cb >> 7;
                const int bh = b * Hq + h;
                const int mblk = l >> 7, trow = l & 127;
#pragma unroll
                for (int j = 0; j < 32; j += 2) {
                    const int col = cb + j;
                    float v0 = __uint_as_float(rr[j])     + bias[col];
                    float v1 = __uint_as_float(rr[j + 1]) + bias[col + 1];
                    if (which == 0) { v0 *= QSCALE2; v1 *= QSCALE2; }
                    const int hd = col & 127, kt = hd >> 6, tc = hd & 63;
                    const size_t base = ((size_t)((bh * 4 + mblk) * 2 + kt)) * 16384;
                    *reinterpret_cast<uint32_t*>(dst + base + swz((uint32_t)(trow * 128 + tc * 2)))
                        = h2u(v0, v1);
                }
            } else {
#pragma unroll
                for (int j = 0; j < 32; j += 2) {
                    const int col = cb + j;
                    float2 v;
                    v.x = __uint_as_float(rr[j])     + bias[col];
                    v.y = __uint_as_float(rr[j + 1]) + bias[col + 1];
                    *reinterpret_cast<float2*>(&outp[(size_t)m * Dq + col]) = v;
                }
            }
        }
    }

    __syncthreads();
    if (wid == 0) {
        TCGEN05_RELINQ();
        TCGEN05_DEALLOC(tmem, 512);
    }
#endif  // HAS_TCG
}

// ==========================================================================
// V transpose -> V^T SW128 tiles. 64x64 blocks, fully vectorized 16B I/O.
// ==========================================================================
__global__ void vt_k() {
    __shared__ __half t[64][72];
    const int bh = blockIdx.z;
    const int l0 = blockIdx.x * 64, d0 = blockIdx.y * 64;
    const int tid = threadIdx.x;
    const __half* src = g_vh + (size_t)bh * Lq * HDq;
#pragma unroll
    for (int i = 0; i < 2; i++) {
        const int u = tid + i * 256;
        const int l = u >> 3, c8 = u & 7;
        const uint4 v = *reinterpret_cast<const uint4*>(&src[(size_t)(l0 + l) * HDq + d0 + c8 * 8]);
        *reinterpret_cast<uint4*>(&t[l][c8 * 8]) = v;
    }
    __syncthreads();
    const int lblk = blockIdx.x;
    const int jblk = lblk >> 1, lt = lblk & 1;
    char* tb = (char*)g_vt + ((size_t)((bh * 4 + jblk) * 2 + lt)) * 16384;
#pragma unroll
    for (int i = 0; i < 2; i++) {
        const int u = tid + i * 256;
        const int d = u & 63, c8 = u >> 6;
        __half h[8];
#pragma unroll
        for (int j = 0; j < 8; j++) h[j] = t[c8 * 8 + j][d];
        const uint32_t off = swz((uint32_t)((d0 + d) * 128 + c8 * 16));
        *reinterpret_cast<uint4*>(tb + off) = *reinterpret_cast<uint4*>(h);
    }
}

// ==========================================================================
// tcgen05 flash attention v3 (R13 exact): one CTA per bh, mb 0..3, O ping-
// pong. 288 threads. TMEM: O0 @0, O1 @128, S0 @256, S1 @384.
// ==========================================================================
__global__ __launch_bounds__(288, 1) void fa_k() {
#if HAS_TCG
    extern __shared__ char smem[];
    const uint32_t sb = smem_u32(smem);
    const uint32_t qful = sb + 16, qfree = sb + 24;
    const uint32_t kvfl[2] = {sb + 32, sb + 40};
    const uint32_t kvfr[2] = {sb + 48, sb + 56};
    const uint32_t sful[2] = {sb + 64, sb + 72};
    const uint32_t sdon[2] = {sb + 80, sb + 88};
    const uint32_t pready = sb + 96, pvdone = sb + 104;
    const uint32_t odon[2]   = {sb + 112, sb + 120};
    const uint32_t oefree[2] = {sb + 128, sb + 136};
    const uint32_t stg0 = (sb + 256 + 1023) & ~1023u;
    const uint32_t qoff = stg0, kvoff = stg0 + 32768, poff = stg0 + 163840;
    char* const psm = smem + (poff - sb);

    const int tid = threadIdx.x, w = tid >> 5, lane = tid & 31;
    const int bh = blockIdx.x;

    if (w == 0) TCGEN05_ALLOC(sb, 512);
    if (tid == 0) {
        MBARRIER_INIT(qful, 1);  MBARRIER_INIT(qfree, 1);
#pragma unroll
        for (int s = 0; s < 2; s++) {
            MBARRIER_INIT(kvfl[s], 1);  MBARRIER_INIT(kvfr[s], 1);
            MBARRIER_INIT(sful[s], 1);  MBARRIER_INIT(sdon[s], 256);
            MBARRIER_INIT(odon[s], 1);  MBARRIER_INIT(oefree[s], 256);
        }
        MBARRIER_INIT(pready, 256);
        MBARRIER_INIT(pvdone, 1);
    }
    __syncthreads();

    uint32_t tmem;
    asm volatile("ld.shared.b32 %0, [%1];" : "=r"(tmem) : "r"(sb));

    const char* Qb = (const char*)g_qh + (size_t)bh * 4 * 32768;
    const char* Kt = (const char*)g_kh + (size_t)bh * 4 * 32768;
    const char* Vt = (const char*)g_vt + (size_t)bh * 4 * 32768;

    if (tid == 256) {
        MBARRIER_EXPECT_TX(qful, 32768);
        bulk_g2s(qoff, Qb, 32768, qful);
        int qfph = 0, frph[2] = {0, 0}, k = 0;
        for (int mb = 0; mb < 4; mb++) {
            for (int jb = 0; jb <= mb; jb++) {
                const int s = k & 1;
                if (k >= 2) { MBARRIER_WAIT_PARITY(kvfr[s], frph[s]); frph[s] ^= 1; }
                MBARRIER_EXPECT_TX(kvfl[s], 65536);
                bulk_g2s(kvoff + s * 65536,         Kt + (size_t)jb * 32768, 32768, kvfl[s]);
                bulk_g2s(kvoff + s * 65536 + 32768, Vt + (size_t)jb * 32768, 32768, kvfl[s]);
                k++;
            }
            if (mb < 3) {
                MBARRIER_WAIT_PARITY(qfree, qfph & 1); qfph++;
                MBARRIER_EXPECT_TX(qful, 32768);
                bulk_g2s(qoff, Qb + (size_t)(mb + 1) * 32768, 32768, qful);
            }
        }
    } else if (tid == 257) {
        const int MB[10] = {0,1,1,2,2,2,3,3,3,3};
        const int JB[10] = {0,0,1,0,1,2,0,1,2,3};
        int qph = 0, kvph[2] = {0,0}, sdph[2] = {0,0}, prph = 0, oeph[2] = {0,0};
        MBARRIER_WAIT_PARITY(qful, 0); qph = 1;
        MBARRIER_WAIT_PARITY(kvfl[0], 0); kvph[0] = 1;
        fa_mma8(tmem + 256, qoff, kvoff, 0);
        TCGEN05_COMMIT(sful[0]);
        TCGEN05_COMMIT(qfree);
        for (int k = 0; k < 10; k++) {
            const int mb = MB[k], jb = JB[k], s = k & 1, ob = mb & 1;
            const bool have_next = (k < 9);
            const bool next_new_q = have_next && (JB[k + 1] == 0);
            if (have_next && !next_new_q) {
                const int s2 = (k + 1) & 1;
                MBARRIER_WAIT_PARITY(kvfl[s2], kvph[s2]); kvph[s2] ^= 1;
                if (k + 1 >= 2) { MBARRIER_WAIT_PARITY(sdon[s2], sdph[s2]); sdph[s2] ^= 1; }
                fa_mma8(tmem + 256 + s2 * 128, qoff, kvoff + s2 * 65536, 0);
                TCGEN05_COMMIT(sful[s2]);
                if (JB[k + 1] == MB[k + 1]) TCGEN05_COMMIT(qfree);
            }
            MBARRIER_WAIT_PARITY(pready, prph & 1); prph++;
            if (jb == 0 && mb >= 2) { MBARRIER_WAIT_PARITY(oefree[ob], oeph[ob]); oeph[ob] ^= 1; }
            fa_mma8(tmem + ob * 128, poff, kvoff + s * 65536 + 32768, (jb > 0) ? 1u : 0u);
            TCGEN05_COMMIT(kvfr[s]);
            TCGEN05_COMMIT(pvdone);
            if (jb == mb) TCGEN05_COMMIT(odon[ob]);
            if (have_next && next_new_q) {
                const int s2 = (k + 1) & 1;
                MBARRIER_WAIT_PARITY(qful, qph & 1); qph++;
                MBARRIER_WAIT_PARITY(kvfl[s2], kvph[s2]); kvph[s2] ^= 1;
                if (k + 1 >= 2) { MBARRIER_WAIT_PARITY(sdon[s2], sdph[s2]); sdph[s2] ^= 1; }
                fa_mma8(tmem + 256 + s2 * 128, qoff, kvoff + s2 * 65536, 0);
                TCGEN05_COMMIT(sful[s2]);
                if (JB[k + 1] == MB[k + 1]) TCGEN05_COMMIT(qfree);
            }
        }
    }

    if (tid < 256) {
        int sfph[2] = {0, 0}, pvph = 0, odph[2] = {0, 0};
        const int rl = (w & 3) * 32 + lane;
        const int cb = (w >> 2) * 64;
        int k = 0;
        const int b2 = bh >> 5, h2 = bh & 31;
        char* aob = (char*)g_AO16;
        const int ktc = (h2 * 128 + cb) >> 6;
        for (int mb = 0; mb < 4; mb++) {
            float lrow = 0.f;
            const int ob = mb & 1;
            for (int jb = 0; jb <= mb; jb++) {
                const int s = k & 1;
                MBARRIER_WAIT_PARITY(sful[s], sfph[s]); sfph[s] ^= 1;
                TCGEN05_FENCE_AFTER();
                uint32_t r[64];
                TCGEN05_LD_X32(r,      tmem + 256 + s * 128 + cb);
                TCGEN05_LD_X32(r + 32, tmem + 256 + s * 128 + cb + 32);
                TCGEN05_WAIT_LD();
                MBARRIER_ARRIVE(sdon[s]);
                if (k > 0) { MBARRIER_WAIT_PARITY(pvdone, pvph & 1); pvph++; }
                const bool diag = (jb == mb);
#pragma unroll
                for (int c = 0; c < 64; c += 8) {
                    float p[8];
#pragma unroll
                    for (int j = 0; j < 8; j++) {
                        float e;
                        asm("ex2.approx.f32 %0, %1;" : "=f"(e) : "f"(__uint_as_float(r[c + j])));
                        p[j] = (diag && (cb + c + j) > rl) ? 0.f : e;
                        lrow += p[j];
                    }
                    uint4 o;
                    o.x = h2u(p[0], p[1]); o.y = h2u(p[2], p[3]);
                    o.z = h2u(p[4], p[5]); o.w = h2u(p[6], p[7]);
                    const uint32_t off = (uint32_t)((cb >> 6) * 16384)
                                         + swz((uint32_t)(rl * 128 + c * 2));
                    *reinterpret_cast<uint4*>(psm + off) = o;
                }
                FENCE_PROXY_ASYNC();
                MBARRIER_ARRIVE(pready);
                k++;
            }
            MBARRIER_WAIT_PARITY(odon[ob], odph[ob]); odph[ob] ^= 1;
            TCGEN05_FENCE_AFTER();
            *reinterpret_cast<float*>(psm + ((cb >> 6) * 128 + rl) * 4) = lrow;
            BAR_CMP();
            const float ltot = *reinterpret_cast<float*>(psm + rl * 4)
                             + *reinterpret_cast<float*>(psm + (128 + rl) * 4);
            BAR_CMP();
            uint32_t r[64];
            TCGEN05_LD_X32(r,      tmem + ob * 128 + cb);
            TCGEN05_LD_X32(r + 32, tmem + ob * 128 + cb + 32);
            TCGEN05_WAIT_LD();
            const float inv = 1.f / ltot;
            const int R = b2 * Lq + mb * 128 + rl;
            const int mb2 = R >> 7, rrow = R & 127;
#pragma unroll
            for (int c = 0; c < 64; c += 8) {
                uint4 o;
                o.x = h2u(__uint_as_float(r[c])     * inv, __uint_as_float(r[c + 1]) * inv);
                o.y = h2u(__uint_as_float(r[c + 2]) * inv, __uint_as_float(r[c + 3]) * inv);
                o.z = h2u(__uint_as_float(r[c + 4]) * inv, __uint_as_float(r[c + 5]) * inv);
                o.w = h2u(__uint_as_float(r[c + 6]) * inv, __uint_as_float(r[c + 7]) * inv);
                *reinterpret_cast<uint4*>(aob + ((size_t)(mb2 * NKT16 + ktc)) * A_TB
                                              + swz((uint32_t)(rrow * 128 + c * 2))) = o;
            }
            MBARRIER_ARRIVE(oefree[ob]);
        }
    }

    __syncthreads();
    if (w == 0) {
        TCGEN05_RELINQ();
        TCGEN05_DEALLOC(tmem, 512);
    }
#endif  // HAS_TCG
}

// ==========================================================================
extern "C" void kernel_launch(void* const* d_in, const int* in_sizes, int n_in,
                              void* d_out, int out_size) {
    const float* x  = (const float*)d_in[0];
    const float* Wq = (const float*)d_in[1];
    const float* bq = (const float*)d_in[2];
    const float* Wk = (const float*)d_in[3];
    const float* bk = (const float*)d_in[4];
    const float* Wv = (const float*)d_in[5];
    const float* bv = (const float*)d_in[6];
    const float* Wo = (const float*)d_in[7];
    const float* bo = (const float*)d_in[8];
    float* out = (float*)d_out;

    cudaFuncSetAttribute(gemm_tc, cudaFuncAttributeMaxDynamicSharedMemorySize, GEMM_SMEM);
    cudaFuncSetAttribute(fa_k,    cudaFuncAttributeMaxDynamicSharedMemorySize, GEMM_SMEM);

    // 1) fused prepass (single launch): y 0-3 weights, y 4-7 x quarters
    prep_all<<<dim3(8192, 8), 256>>>((const float4*)x, (const float4*)Wq,
                                     (const float4*)Wk, (const float4*)Wv,
                                     (const float4*)Wo);

    // 2) fused Q/K/V projections
    gemm_tc<<<dim3(16, 192), 128, GEMM_SMEM>>>(bq, bk, bv, nullptr, 0);

    // 3) attention (fa_k is 4th launch -> profiled slot)
    vt_k<<<dim3(8, 2, BHq), 256>>>();
    fa_k<<<BHq, 288, GEMM_SMEM>>>();

    // 4) output projection
    gemm_tc<<<dim3(16, 64), 128, GEMM_SMEM>>>(bo, bo, bo, out, 1);
}